// round 5
// baseline (speedup 1.0000x reference)
#include <cuda_runtime.h>
#include <cuda_bf16.h>
#include <cstdint>

#define F 128
#define NN 50000
#define NE 800000

#define TM 96              // rows per CTA tile
// ---- smem layout (bytes): all tiles row-major 256B/row, XOR-swizzled ----
#define OFF_WHI 0u
#define OFF_WLO 32768u
#define OFF_AHI 65536u     // 96*256
#define OFF_ALO 90112u
#define SMEM_REQ 114688u

// ---------------- persistent device scratch ----------------
__device__ float g_P[(size_t)NN * F];
__device__ float g_S[(size_t)NN * F];
__device__ float g_H[(size_t)NN * F];
__device__ float g_T[(size_t)NN * F];
__device__ float g_deg[NN];

// ---------------- low-level helpers ----------------
__device__ __forceinline__ uint32_t cvta_smem(const void* p) {
    uint32_t a;
    asm("{ .reg .u64 t; cvta.to.shared.u64 t, %1; cvt.u32.u64 %0, t; }" : "=r"(a) : "l"(p));
    return a;
}
// byte offset of bf16 (r, c) in swizzled tile: 256B rows, 16B units XOR'd by r&7
__device__ __forceinline__ uint32_t swoff(int r, int c) {
    return (uint32_t)(r * 256) + (uint32_t)((((c >> 3) ^ (r & 7)) << 4) + (c & 7) * 2);
}

__device__ __forceinline__ void ldsm4(uint32_t addr, uint32_t& r0, uint32_t& r1,
                                      uint32_t& r2, uint32_t& r3) {
    asm volatile("ldmatrix.sync.aligned.m8n8.x4.shared.b16 {%0,%1,%2,%3}, [%4];"
                 : "=r"(r0), "=r"(r1), "=r"(r2), "=r"(r3) : "r"(addr));
}
__device__ __forceinline__ void ldsm2(uint32_t addr, uint32_t& r0, uint32_t& r1) {
    asm volatile("ldmatrix.sync.aligned.m8n8.x2.shared.b16 {%0,%1}, [%2];"
                 : "=r"(r0), "=r"(r1) : "r"(addr));
}

__device__ __forceinline__ void mma_bf16(float* c, uint32_t a0, uint32_t a1, uint32_t a2,
                                         uint32_t a3, uint32_t b0, uint32_t b1) {
    asm volatile("mma.sync.aligned.m16n8k16.row.col.f32.bf16.bf16.f32 "
                 "{%0,%1,%2,%3}, {%4,%5,%6,%7}, {%8,%9}, {%0,%1,%2,%3};"
                 : "+f"(c[0]), "+f"(c[1]), "+f"(c[2]), "+f"(c[3])
                 : "r"(a0), "r"(a1), "r"(a2), "r"(a3), "r"(b0), "r"(b1));
}

__device__ __forceinline__ void splitf(float x, __nv_bfloat16* hi, __nv_bfloat16* lo) {
    __nv_bfloat16 h = __float2bfloat16(x);
    *hi = h;
    *lo = __float2bfloat16(x - __bfloat162float(h));
}
__device__ __forceinline__ uint32_t pack2(__nv_bfloat16 a, __nv_bfloat16 b) {
    __nv_bfloat162 v; v.x = a; v.y = b;
    return *reinterpret_cast<uint32_t*>(&v);
}

__global__ void zero_kernel() {
    size_t stride = (size_t)gridDim.x * blockDim.x;
    size_t gid = (size_t)blockIdx.x * blockDim.x + threadIdx.x;
    float4 z = make_float4(0.f, 0.f, 0.f, 0.f);
    float4* S4 = reinterpret_cast<float4*>(g_S);
    for (size_t i = gid; i < (size_t)NN * F / 4; i += stride) S4[i] = z;
    for (size_t i = gid; i < (size_t)NN; i += stride) g_deg[i] = 0.f;
}

// ---------------- persistent fused GEMM, 2 CTAs/SM ----------------
// Column permutation: accumulator col (nt*8 + 2t + i) holds PHYSICAL col (8t + 2nt + i),
// arranged by staging smem B[n'] from weight col p(n') = 8*((n'&7)>>1) + 2*((n'>>3)&3) + (n'&1).
// => each thread owns 8 contiguous physical cols [8t, 8t+8) per row: reg->gmem epilogue.
__global__ void __launch_bounds__(384, 2)
gnn_gemm(const float* __restrict__ A, const float* __restrict__ Wg,
         const float* __restrict__ bias, const float* __restrict__ rowscale,
         const float* __restrict__ residual, float* __restrict__ outp,
         const int* __restrict__ src, const int* __restrict__ dst,
         int M, int ntiles, int do_relu, int is_edge) {
    extern __shared__ char sm[];
    const uint32_t sb = cvta_smem(sm);
    const int tid = threadIdx.x;

    // ---- stage weights once: smem[n'][k] = Wg[k][perm(n')], split hi/lo, swizzled ----
    for (int idx = tid; idx < 4096; idx += 384) {        // 128 n' x 32 k-groups
        int np = idx >> 5;
        int k0 = (idx & 31) << 2;
        int pl = 8 * ((np & 7) >> 1) + 2 * ((np >> 3) & 3) + (np & 1);
        int p = (np & ~31) | pl;
        uint32_t o = swoff(np, k0);
        __nv_bfloat16 h0, l0, h1, l1, h2, l2, h3, l3;
        splitf(__ldg(Wg + (k0 + 0) * F + p), &h0, &l0);
        splitf(__ldg(Wg + (k0 + 1) * F + p), &h1, &l1);
        splitf(__ldg(Wg + (k0 + 2) * F + p), &h2, &l2);
        splitf(__ldg(Wg + (k0 + 3) * F + p), &h3, &l3);
        *reinterpret_cast<uint2*>(sm + OFF_WHI + o) = make_uint2(pack2(h0, h1), pack2(h2, h3));
        *reinterpret_cast<uint2*>(sm + OFF_WLO + o) = make_uint2(pack2(l0, l1), pack2(l2, l3));
    }

    const int w = tid >> 5, lane = tid & 31;
    const int wr = w >> 2, wc = w & 3;          // 3 row-groups x 4 col-groups
    const int g = lane >> 2, t = lane & 3;

    // ldmatrix lane rows/cols
    const int raL = ((lane >> 3) & 1) * 8 + (lane & 7);
    const int kaL = ((lane >> 4) & 1) * 8;
    const int nbL = lane & 7;
    const int kbL = ((lane >> 3) & 1) * 8;

    __syncthreads();

    for (int tile = blockIdx.x; tile < ntiles; tile += gridDim.x) {
        const int row0 = tile * TM;

        // ---- LDG + split + STS A (96 x 128 fp32 -> hi/lo swizzled) ----
        for (int i = 0; i < 8; i++) {
            int idx = tid + i * 384;                     // 3072 float4
            int r = idx >> 5;
            int c = (idx & 31) << 2;
            int gr = row0 + r;
            float4 v = make_float4(0.f, 0.f, 0.f, 0.f);
            if (gr < M) v = __ldg(reinterpret_cast<const float4*>(A + (size_t)gr * F + c));
            __nv_bfloat16 h0, l0, h1, l1, h2, l2, h3, l3;
            splitf(v.x, &h0, &l0); splitf(v.y, &h1, &l1);
            splitf(v.z, &h2, &l2); splitf(v.w, &h3, &l3);
            uint32_t o = swoff(r, c);
            *reinterpret_cast<uint2*>(sm + OFF_AHI + o) = make_uint2(pack2(h0, h1), pack2(h2, h3));
            *reinterpret_cast<uint2*>(sm + OFF_ALO + o) = make_uint2(pack2(l0, l1), pack2(l2, l3));
        }
        __syncthreads();

        // ---- 96x128x128 bf16x3 MMA, acc resident ----
        float acc[2][4][4];
#pragma unroll
        for (int mt = 0; mt < 2; mt++)
#pragma unroll
            for (int nt = 0; nt < 4; nt++)
#pragma unroll
                for (int i = 0; i < 4; i++) acc[mt][nt][i] = 0.f;

#pragma unroll
        for (int ks = 0; ks < 8; ks++) {
            uint32_t ah[2][4], al[2][4];
#pragma unroll
            for (int mt = 0; mt < 2; mt++) {
                int ra = wr * 32 + mt * 16 + raL;
                uint32_t ao = swoff(ra, ks * 16 + kaL);
                ldsm4(sb + OFF_AHI + ao, ah[mt][0], ah[mt][1], ah[mt][2], ah[mt][3]);
                ldsm4(sb + OFF_ALO + ao, al[mt][0], al[mt][1], al[mt][2], al[mt][3]);
            }
#pragma unroll
            for (int nt = 0; nt < 4; nt++) {
                int nb = wc * 32 + nt * 8 + nbL;
                uint32_t bo = swoff(nb, ks * 16 + kbL);
                uint32_t bh0, bh1, bl0, bl1;
                ldsm2(sb + OFF_WHI + bo, bh0, bh1);
                ldsm2(sb + OFF_WLO + bo, bl0, bl1);
#pragma unroll
                for (int mt = 0; mt < 2; mt++) {
                    mma_bf16(acc[mt][nt], ah[mt][0], ah[mt][1], ah[mt][2], ah[mt][3], bh0, bh1);
                    mma_bf16(acc[mt][nt], al[mt][0], al[mt][1], al[mt][2], al[mt][3], bh0, bh1);
                    mma_bf16(acc[mt][nt], ah[mt][0], ah[mt][1], ah[mt][2], ah[mt][3], bl0, bl1);
                }
            }
        }

        // ---- epilogue straight from accumulators (physical cols cb..cb+7) ----
        const int cb = wc * 32 + 8 * t;
        if (is_edge) {
#pragma unroll
            for (int mt = 0; mt < 2; mt++)
#pragma unroll
                for (int v = 0; v < 2; v++) {
                    int r = wr * 32 + mt * 16 + v * 8 + g;
                    int e = row0 + r;
                    if (e < M) {
                        int s = __ldg(src + e);
                        int d = __ldg(dst + e);
                        const float4* Pr = reinterpret_cast<const float4*>(g_P + (size_t)s * F + cb);
                        float* Sr = g_S + (size_t)d * F + cb;
#pragma unroll
                        for (int h = 0; h < 2; h++) {
                            float4 p = __ldg(Pr + h);
                            float x0 = fmaxf(acc[mt][2*h][2*v]     + p.x, 0.f);
                            float x1 = fmaxf(acc[mt][2*h][2*v+1]   + p.y, 0.f);
                            float x2 = fmaxf(acc[mt][2*h+1][2*v]   + p.z, 0.f);
                            float x3 = fmaxf(acc[mt][2*h+1][2*v+1] + p.w, 0.f);
                            asm volatile("red.global.add.v4.f32 [%0], {%1,%2,%3,%4};"
                                         :: "l"(Sr + 4 * h), "f"(x0), "f"(x1), "f"(x2), "f"(x3)
                                         : "memory");
                        }
                        if (wc == 0 && t == 0) atomicAdd(&g_deg[d], 1.0f);
                    }
                }
        } else {
#pragma unroll
            for (int mt = 0; mt < 2; mt++)
#pragma unroll
                for (int v = 0; v < 2; v++) {
                    int r = wr * 32 + mt * 16 + v * 8 + g;
                    int gr = row0 + r;
                    if (gr < M) {
                        float rs = rowscale ? __ldg(rowscale + gr) : 1.f;
#pragma unroll
                        for (int h = 0; h < 2; h++) {
                            float4 bb = __ldg(reinterpret_cast<const float4*>(bias + cb) + h);
                            float4 o;
                            o.x = acc[mt][2*h][2*v]     + rs * bb.x;
                            o.y = acc[mt][2*h][2*v+1]   + rs * bb.y;
                            o.z = acc[mt][2*h+1][2*v]   + rs * bb.z;
                            o.w = acc[mt][2*h+1][2*v+1] + rs * bb.w;
                            if (residual) {
                                float4 q = __ldg(reinterpret_cast<const float4*>(
                                                 residual + (size_t)gr * F + cb) + h);
                                o.x += q.x; o.y += q.y; o.z += q.z; o.w += q.w;
                            }
                            if (do_relu) {
                                o.x = fmaxf(o.x, 0.f); o.y = fmaxf(o.y, 0.f);
                                o.z = fmaxf(o.z, 0.f); o.w = fmaxf(o.w, 0.f);
                            }
                            *(reinterpret_cast<float4*>(outp + (size_t)gr * F + cb) + h) = o;
                        }
                    }
                }
        }
        __syncthreads();   // A-smem reads (ldmatrix) done in all warps before next STS
    }
}

// ---------------- launch ----------------
extern "C" void kernel_launch(void* const* d_in, const int* in_sizes, int n_in,
                              void* d_out, int out_size) {
    const float* node  = (const float*)d_in[0];
    const float* edgef = (const float*)d_in[1];
    const int*   src   = (const int*)  d_in[2];
    const int*   dst   = (const int*)  d_in[3];
    const float* W1a   = (const float*)d_in[4];
    const float* b1a   = (const float*)d_in[5];
    const float* W1b   = (const float*)d_in[6];
    const float* b1b   = (const float*)d_in[7];
    const float* W2a   = (const float*)d_in[8];
    const float* b2a   = (const float*)d_in[9];
    const float* W2b   = (const float*)d_in[10];
    const float* b2b   = (const float*)d_in[11];
    float* out = (float*)d_out;

    cudaFuncSetAttribute(gnn_gemm, cudaFuncAttributeMaxDynamicSharedMemorySize, (int)SMEM_REQ);

    float *P, *S, *H, *T, *deg;
    cudaGetSymbolAddress((void**)&P,   g_P);
    cudaGetSymbolAddress((void**)&S,   g_S);
    cudaGetSymbolAddress((void**)&H,   g_H);
    cudaGetSymbolAddress((void**)&T,   g_T);
    cudaGetSymbolAddress((void**)&deg, g_deg);

    const int nodeTiles = (NN + TM - 1) / TM;   // 521
    const int edgeTiles = (NE + TM - 1) / TM;   // 8334
    const int GRID = 296;                       // 2 CTAs / SM

    zero_kernel<<<512, 256>>>();
    // P = node @ W1a_top + b1a
    gnn_gemm<<<GRID, 384, SMEM_REQ>>>(node, W1a, b1a, nullptr, nullptr, P,
                                      nullptr, nullptr, NN, nodeTiles, 0, 0);
    // edge: relu(E @ W1a_bot + P[src]) scatter-added into S[dst]; deg counts
    gnn_gemm<<<GRID, 384, SMEM_REQ>>>(edgef, W1a + F * F, nullptr, nullptr, nullptr, nullptr,
                                      src, dst, NE, edgeTiles, 0, 1);
    // H = S @ W1b + deg*b1b + node
    gnn_gemm<<<GRID, 384, SMEM_REQ>>>(S, W1b, b1b, deg, node, H,
                                      nullptr, nullptr, NN, nodeTiles, 0, 0);
    // T = relu(H @ W2a + b2a)
    gnn_gemm<<<GRID, 384, SMEM_REQ>>>(H, W2a, b2a, nullptr, nullptr, T,
                                      nullptr, nullptr, NN, nodeTiles, 1, 0);
    // out = T @ W2b + b2b
    gnn_gemm<<<GRID, 384, SMEM_REQ>>>(T, W2b, b2b, nullptr, nullptr, out,
                                      nullptr, nullptr, NN, nodeTiles, 0, 0);
}

// round 7
// speedup vs baseline: 1.3584x; 1.3584x over previous
#include <cuda_runtime.h>
#include <cuda_bf16.h>
#include <cstdint>

#define F 128
#define NN 50000
#define NE 800000

#define TM 96              // rows per CTA tile
// ---- smem layout (bytes): weights image [hi 32K | lo 32K], A split tiles ----
#define OFF_WHI 0u
#define OFF_WLO 32768u
#define OFF_AHI 65536u     // 96*256
#define OFF_ALO 90112u
#define SMEM_REQ 114688u   // 112 KB -> 2 CTAs/SM

// ---------------- persistent device scratch ----------------
__device__ __align__(32) float g_P[(size_t)NN * F];
__device__ __align__(32) float g_S[(size_t)NN * F];
__device__ __align__(32) float g_H[(size_t)NN * F];
__device__ __align__(32) float g_T[(size_t)NN * F];
__device__ float g_deg[NN];
// pre-split / pre-permuted / pre-swizzled weight images (exact smem layout)
__device__ __align__(16) uint8_t g_Wimg[5][65536];

// ---------------- low-level helpers ----------------
__device__ __forceinline__ uint32_t cvta_smem(const void* p) {
    uint32_t a;
    asm("{ .reg .u64 t; cvta.to.shared.u64 t, %1; cvt.u32.u64 %0, t; }" : "=r"(a) : "l"(p));
    return a;
}
// byte offset of bf16 (r, c) in swizzled tile: 256B rows, 16B units XOR'd by r&7
__device__ __forceinline__ uint32_t swoff(int r, int c) {
    return (uint32_t)(r * 256) + (uint32_t)((((c >> 3) ^ (r & 7)) << 4) + (c & 7) * 2);
}

__device__ __forceinline__ void ldsm4(uint32_t addr, uint32_t& r0, uint32_t& r1,
                                      uint32_t& r2, uint32_t& r3) {
    asm volatile("ldmatrix.sync.aligned.m8n8.x4.shared.b16 {%0,%1,%2,%3}, [%4];"
                 : "=r"(r0), "=r"(r1), "=r"(r2), "=r"(r3) : "r"(addr));
}

__device__ __forceinline__ void mma_bf16(float* c, uint32_t a0, uint32_t a1, uint32_t a2,
                                         uint32_t a3, uint32_t b0, uint32_t b1) {
    asm volatile("mma.sync.aligned.m16n8k16.row.col.f32.bf16.bf16.f32 "
                 "{%0,%1,%2,%3}, {%4,%5,%6,%7}, {%8,%9}, {%0,%1,%2,%3};"
                 : "+f"(c[0]), "+f"(c[1]), "+f"(c[2]), "+f"(c[3])
                 : "r"(a0), "r"(a1), "r"(a2), "r"(a3), "r"(b0), "r"(b1));
}

__device__ __forceinline__ void splitf(float x, __nv_bfloat16* hi, __nv_bfloat16* lo) {
    __nv_bfloat16 h = __float2bfloat16(x);
    *hi = h;
    *lo = __float2bfloat16(x - __bfloat162float(h));
}
__device__ __forceinline__ uint32_t pack2(__nv_bfloat16 a, __nv_bfloat16 b) {
    __nv_bfloat162 v; v.x = a; v.y = b;
    return *reinterpret_cast<uint32_t*>(&v);
}

// streaming 32B read with evict_first (v4.b64 form required by this ptxas)
__device__ __forceinline__ void ldg_stream8(const float* p, float* f) {
    unsigned long long u0, u1, u2, u3;
    asm volatile("ld.global.nc.L2::evict_first.v4.b64 {%0,%1,%2,%3}, [%4];"
                 : "=l"(u0), "=l"(u1), "=l"(u2), "=l"(u3) : "l"(p));
    f[0] = __uint_as_float((uint32_t)u0); f[1] = __uint_as_float((uint32_t)(u0 >> 32));
    f[2] = __uint_as_float((uint32_t)u1); f[3] = __uint_as_float((uint32_t)(u1 >> 32));
    f[4] = __uint_as_float((uint32_t)u2); f[5] = __uint_as_float((uint32_t)(u2 >> 32));
    f[6] = __uint_as_float((uint32_t)u3); f[7] = __uint_as_float((uint32_t)(u3 >> 32));
}

__device__ __forceinline__ void cp16(uint32_t dst, const void* src) {
    asm volatile("cp.async.cg.shared.global [%0], [%1], 16;" :: "r"(dst), "l"(src) : "memory");
}
__device__ __forceinline__ void cp_commit() { asm volatile("cp.async.commit_group;" ::: "memory"); }
__device__ __forceinline__ void cp_wait0()  { asm volatile("cp.async.wait_group 0;"  ::: "memory"); }

// ---------------- one-time weight image build ----------------
// image layout == smem layout: smem[n'][k] = W[k][perm(n')], hi at swoff, lo at 32768+swoff
__global__ void prep_kernel(const float* __restrict__ W1a, const float* __restrict__ W1b,
                            const float* __restrict__ W2a, const float* __restrict__ W2b) {
    int gid = blockIdx.x * blockDim.x + threadIdx.x;
    if (gid >= 5 * 4096) return;
    int img = gid >> 12;
    int idx = gid & 4095;
    int np = idx >> 5;
    int k0 = (idx & 31) << 2;
    int pl = 8 * ((np & 7) >> 1) + 2 * ((np >> 3) & 3) + (np & 1);
    int p = (np & ~31) | pl;
    const float* src = (img == 0) ? W1a
                     : (img == 1) ? (W1a + F * F)
                     : (img == 2) ? W1b
                     : (img == 3) ? W2a : W2b;
    __nv_bfloat16 h0, l0, h1, l1, h2, l2, h3, l3;
    splitf(__ldg(src + (k0 + 0) * F + p), &h0, &l0);
    splitf(__ldg(src + (k0 + 1) * F + p), &h1, &l1);
    splitf(__ldg(src + (k0 + 2) * F + p), &h2, &l2);
    splitf(__ldg(src + (k0 + 3) * F + p), &h3, &l3);
    uint32_t o = swoff(np, k0);
    *reinterpret_cast<uint2*>(&g_Wimg[img][o])          = make_uint2(pack2(h0, h1), pack2(h2, h3));
    *reinterpret_cast<uint2*>(&g_Wimg[img][32768 + o])  = make_uint2(pack2(l0, l1), pack2(l2, l3));
}

__global__ void zero_kernel() {
    size_t stride = (size_t)gridDim.x * blockDim.x;
    size_t gid = (size_t)blockIdx.x * blockDim.x + threadIdx.x;
    float4 z = make_float4(0.f, 0.f, 0.f, 0.f);
    float4* S4 = reinterpret_cast<float4*>(g_S);
    for (size_t i = gid; i < (size_t)NN * F / 4; i += stride) S4[i] = z;
    for (size_t i = gid; i < (size_t)NN; i += stride) g_deg[i] = 0.f;
}

// ---------------- persistent fused GEMM, 2 CTAs/SM ----------------
// Column permutation baked into weight image: acc col (nt*8+2t+i) == physical col (8t+2nt+i);
// each thread owns 8 contiguous physical cols [8t,8t+8) per row -> reg->gmem epilogue.
__global__ void __launch_bounds__(384, 2)
gnn_gemm(const float* __restrict__ A, int wimg,
         const float* __restrict__ bias, const float* __restrict__ rowscale,
         const float* __restrict__ residual, float* __restrict__ outp,
         const int* __restrict__ src, const int* __restrict__ dst,
         int M, int ntiles, int do_relu, int is_edge) {
    extern __shared__ char sm[];
    const uint32_t sb = cvta_smem(sm);
    const int tid = threadIdx.x;

    // ---- stage weight image: linear coalesced 64KB cp.async ----
    {
        const uint8_t* wsrc = &g_Wimg[wimg][0];
        for (int i = tid; i < 4096; i += 384)
            cp16(sb + (uint32_t)i * 16u, wsrc + i * 16);
        cp_commit();
    }

    const int w = tid >> 5, lane = tid & 31;
    const int wr = w >> 2, wc = w & 3;          // 3 row-groups x 4 col-groups
    const int g = lane >> 2, t = lane & 3;

    // ldmatrix lane rows/cols
    const int raL = ((lane >> 3) & 1) * 8 + (lane & 7);
    const int kaL = ((lane >> 4) & 1) * 8;
    const int rbL = ((lane >> 4) & 1) * 8 + (lane & 7);   // B x4: bit4 -> nt within pair
    const int kbL = ((lane >> 3) & 1) * 8;                //        bit3 -> k half

    bool first = true;
    for (int tile = blockIdx.x; tile < ntiles; tile += gridDim.x) {
        const int row0 = tile * TM;

        // ---- LDG (streaming, evict_first, 32B/thread) + split + STS A ----
        for (int i = 0; i < 4; i++) {
            int idx = tid + i * 384;                     // 1536 chunks of 8 floats
            int r = idx >> 4;
            int c = (idx & 15) << 3;
            int gr = row0 + r;
            float f[8] = {0.f, 0.f, 0.f, 0.f, 0.f, 0.f, 0.f, 0.f};
            if (gr < M) ldg_stream8(A + (size_t)gr * F + c, f);
            __nv_bfloat16 h[8], l[8];
#pragma unroll
            for (int j = 0; j < 8; j++) splitf(f[j], &h[j], &l[j]);
            uint32_t o = swoff(r, c);   // c multiple of 8 -> one 16B unit
            *reinterpret_cast<uint4*>(sm + OFF_AHI + o) =
                make_uint4(pack2(h[0], h[1]), pack2(h[2], h[3]), pack2(h[4], h[5]), pack2(h[6], h[7]));
            *reinterpret_cast<uint4*>(sm + OFF_ALO + o) =
                make_uint4(pack2(l[0], l[1]), pack2(l[2], l[3]), pack2(l[4], l[5]), pack2(l[6], l[7]));
        }
        if (first) { cp_wait0(); first = false; }
        __syncthreads();

        // ---- 96x128x128 bf16x3 MMA, acc resident ----
        float acc[2][4][4];
#pragma unroll
        for (int mt = 0; mt < 2; mt++)
#pragma unroll
            for (int nt = 0; nt < 4; nt++)
#pragma unroll
                for (int i = 0; i < 4; i++) acc[mt][nt][i] = 0.f;

#pragma unroll
        for (int ks = 0; ks < 8; ks++) {
            uint32_t ah[2][4], al[2][4];
#pragma unroll
            for (int mt = 0; mt < 2; mt++) {
                int ra = wr * 32 + mt * 16 + raL;
                uint32_t ao = swoff(ra, ks * 16 + kaL);
                ldsm4(sb + OFF_AHI + ao, ah[mt][0], ah[mt][1], ah[mt][2], ah[mt][3]);
                ldsm4(sb + OFF_ALO + ao, al[mt][0], al[mt][1], al[mt][2], al[mt][3]);
            }
            uint32_t bh[4][2], bl[4][2];
#pragma unroll
            for (int ntp = 0; ntp < 2; ntp++) {
                int nb = wc * 32 + ntp * 16 + rbL;
                uint32_t bo = swoff(nb, ks * 16 + kbL);
                ldsm4(sb + OFF_WHI + bo, bh[2*ntp][0], bh[2*ntp][1], bh[2*ntp+1][0], bh[2*ntp+1][1]);
                ldsm4(sb + OFF_WLO + bo, bl[2*ntp][0], bl[2*ntp][1], bl[2*ntp+1][0], bl[2*ntp+1][1]);
            }
#pragma unroll
            for (int nt = 0; nt < 4; nt++)
#pragma unroll
                for (int mt = 0; mt < 2; mt++) {
                    mma_bf16(acc[mt][nt], ah[mt][0], ah[mt][1], ah[mt][2], ah[mt][3],
                             bh[nt][0], bh[nt][1]);
                    mma_bf16(acc[mt][nt], al[mt][0], al[mt][1], al[mt][2], al[mt][3],
                             bh[nt][0], bh[nt][1]);
                    mma_bf16(acc[mt][nt], ah[mt][0], ah[mt][1], ah[mt][2], ah[mt][3],
                             bl[nt][0], bl[nt][1]);
                }
        }

        // ---- epilogue straight from accumulators (physical cols cb..cb+7) ----
        const int cb = wc * 32 + 8 * t;
        if (is_edge) {
#pragma unroll
            for (int mt = 0; mt < 2; mt++)
#pragma unroll
                for (int v = 0; v < 2; v++) {
                    int r = wr * 32 + mt * 16 + v * 8 + g;
                    int e = row0 + r;
                    if (e < M) {
                        int s = __ldg(src + e);
                        int d = __ldg(dst + e);
                        const float4* Pr = reinterpret_cast<const float4*>(g_P + (size_t)s * F + cb);
                        float* Sr = g_S + (size_t)d * F + cb;
#pragma unroll
                        for (int h = 0; h < 2; h++) {
                            float4 p = __ldg(Pr + h);
                            float x0 = fmaxf(acc[mt][2*h][2*v]     + p.x, 0.f);
                            float x1 = fmaxf(acc[mt][2*h][2*v+1]   + p.y, 0.f);
                            float x2 = fmaxf(acc[mt][2*h+1][2*v]   + p.z, 0.f);
                            float x3 = fmaxf(acc[mt][2*h+1][2*v+1] + p.w, 0.f);
                            asm volatile("red.global.add.v4.f32 [%0], {%1,%2,%3,%4};"
                                         :: "l"(Sr + 4 * h), "f"(x0), "f"(x1), "f"(x2), "f"(x3)
                                         : "memory");
                        }
                        if (wc == 0 && t == 0) atomicAdd(&g_deg[d], 1.0f);
                    }
                }
        } else {
#pragma unroll
            for (int mt = 0; mt < 2; mt++)
#pragma unroll
                for (int v = 0; v < 2; v++) {
                    int r = wr * 32 + mt * 16 + v * 8 + g;
                    int gr = row0 + r;
                    if (gr < M) {
                        float rs = rowscale ? __ldg(rowscale + gr) : 1.f;
#pragma unroll
                        for (int h = 0; h < 2; h++) {
                            float4 bb = __ldg(reinterpret_cast<const float4*>(bias + cb) + h);
                            float4 o;
                            o.x = acc[mt][2*h][2*v]     + rs * bb.x;
                            o.y = acc[mt][2*h][2*v+1]   + rs * bb.y;
                            o.z = acc[mt][2*h+1][2*v]   + rs * bb.z;
                            o.w = acc[mt][2*h+1][2*v+1] + rs * bb.w;
                            if (residual) {
                                float4 q = __ldg(reinterpret_cast<const float4*>(
                                                 residual + (size_t)gr * F + cb) + h);
                                o.x += q.x; o.y += q.y; o.z += q.z; o.w += q.w;
                            }
                            if (do_relu) {
                                o.x = fmaxf(o.x, 0.f); o.y = fmaxf(o.y, 0.f);
                                o.z = fmaxf(o.z, 0.f); o.w = fmaxf(o.w, 0.f);
                            }
                            *(reinterpret_cast<float4*>(outp + (size_t)gr * F + cb) + h) = o;
                        }
                    }
                }
        }
        __syncthreads();   // A-smem reads done in all warps before next STS
    }
}

// ---------------- launch ----------------
extern "C" void kernel_launch(void* const* d_in, const int* in_sizes, int n_in,
                              void* d_out, int out_size) {
    const float* node  = (const float*)d_in[0];
    const float* edgef = (const float*)d_in[1];
    const int*   src   = (const int*)  d_in[2];
    const int*   dst   = (const int*)  d_in[3];
    const float* W1a   = (const float*)d_in[4];
    const float* b1a   = (const float*)d_in[5];
    const float* W1b   = (const float*)d_in[6];
    const float* b1b   = (const float*)d_in[7];
    const float* W2a   = (const float*)d_in[8];
    const float* b2a   = (const float*)d_in[9];
    const float* W2b   = (const float*)d_in[10];
    const float* b2b   = (const float*)d_in[11];
    float* out = (float*)d_out;

    cudaFuncSetAttribute(gnn_gemm, cudaFuncAttributeMaxDynamicSharedMemorySize, (int)SMEM_REQ);

    float *P, *S, *H, *T, *deg;
    cudaGetSymbolAddress((void**)&P,   g_P);
    cudaGetSymbolAddress((void**)&S,   g_S);
    cudaGetSymbolAddress((void**)&H,   g_H);
    cudaGetSymbolAddress((void**)&T,   g_T);
    cudaGetSymbolAddress((void**)&deg, g_deg);

    const int nodeTiles = (NN + TM - 1) / TM;   // 521
    const int edgeTiles = (NE + TM - 1) / TM;   // 8334
    const int GRID = 296;                       // 2 CTAs / SM

    prep_kernel<<<80, 256>>>(W1a, W1b, W2a, W2b);
    zero_kernel<<<512, 256>>>();
    // P = node @ W1a_top + b1a
    gnn_gemm<<<GRID, 384, SMEM_REQ>>>(node, 0, b1a, nullptr, nullptr, P,
                                      nullptr, nullptr, NN, nodeTiles, 0, 0);
    // edge: relu(E @ W1a_bot + P[src]) scatter-added into S[dst]; deg counts
    gnn_gemm<<<GRID, 384, SMEM_REQ>>>(edgef, 1, nullptr, nullptr, nullptr, nullptr,
                                      src, dst, NE, edgeTiles, 0, 1);
    // H = S @ W1b + deg*b1b + node
    gnn_gemm<<<GRID, 384, SMEM_REQ>>>(S, 2, b1b, deg, node, H,
                                      nullptr, nullptr, NN, nodeTiles, 0, 0);
    // T = relu(H @ W2a + b2a)
    gnn_gemm<<<GRID, 384, SMEM_REQ>>>(H, 3, b2a, nullptr, nullptr, T,
                                      nullptr, nullptr, NN, nodeTiles, 1, 0);
    // out = T @ W2b + b2b
    gnn_gemm<<<GRID, 384, SMEM_REQ>>>(T, 4, b2b, nullptr, nullptr, out,
                                      nullptr, nullptr, NN, nodeTiles, 0, 0);
}